// round 10
// baseline (speedup 1.0000x reference)
#include <cuda_runtime.h>
#include <cuda_bf16.h>
#include <mma.h>
#include <cstdint>

using namespace nvcuda;

// ---------------------------------------------------------------------------
// Problem constants
// ---------------------------------------------------------------------------
#define NB    8
#define NPIX  9216     // 96*96
#define NREG  512      // R*HEADS
#define NC    256      // channels / E
#define NHEAD 8
#define NHD   32
#define KSPLIT_G 4

// ---------------------------------------------------------------------------
// Scratch (device globals)
// ---------------------------------------------------------------------------
__device__ float         g_L   [(size_t)NB * NPIX * NREG];   // raw logits fp32
__device__ __nv_bfloat16 g_PqT [(size_t)NB * NPIX * NREG];
__device__ __nv_bfloat16 g_PkT [(size_t)NB * NPIX * NREG];
__device__ __nv_bfloat16 g_Pq  [(size_t)NB * NREG * NPIX];
__device__ __nv_bfloat16 g_Pk  [(size_t)NB * NREG * NPIX];
__device__ __nv_bfloat16 g_tgt_bf [(size_t)NB * NC * NPIX];
__device__ __nv_bfloat16 g_src_bf [(size_t)NB * NC * NPIX];
__device__ __nv_bfloat16 g_tgtT_bf[(size_t)NB * NPIX * NC];
__device__ __nv_bfloat16 g_srcT_bf[(size_t)NB * NPIX * NC];
__device__ __nv_bfloat16 g_Wrq_bf[NREG * NC];
__device__ __nv_bfloat16 g_Wrk_bf[NREG * NC];
__device__ float         g_Gp  [(size_t)KSPLIT_G * NB * 2 * NC * NREG];
__device__ float         g_G   [(size_t)NB * 2 * NC * NREG];
__device__ float         g_S   [(size_t)NB * 2 * NREG];
__device__ __nv_bfloat16 g_Mbf [(size_t)NB * NC * NREG];

// ---------------------------------------------------------------------------
// cp.async helpers
// ---------------------------------------------------------------------------
__device__ __forceinline__ uint32_t smem_u32(const void* p) {
    uint32_t a;
    asm("{ .reg .u64 t; cvta.to.shared.u64 t, %1; cvt.u32.u64 %0, t; }"
        : "=r"(a) : "l"(p));
    return a;
}
__device__ __forceinline__ void cp_async16(uint32_t dst, const void* src) {
    asm volatile("cp.async.cg.shared.global [%0], [%1], 16;\n" :: "r"(dst), "l"(src));
}
#define CP_COMMIT()  asm volatile("cp.async.commit_group;\n" ::: "memory")
#define CP_WAIT(n)   asm volatile("cp.async.wait_group %0;\n" :: "n"(n) : "memory")

// ---------------------------------------------------------------------------
// WMMA bf16 GEMM: D[m,n] = sum_k A[m,k]*B[n,k]   (both K-major, NT form)
// CTA tile 128x128, BK=32, 256 threads (8 warps, 4x2), warp tile 32x64.
// MODE=0: raw fp32 store (+optional ksplit partial offset partStride).
// MODE=2: fused residual epilogue C = res + alpha*(acc + rbias[row]).
// ---------------------------------------------------------------------------
template<int MODE>
__global__ __launch_bounds__(256) void gemm_wmma_kernel(
    const __nv_bfloat16* __restrict__ A, int lda, long strideA,
    const __nv_bfloat16* __restrict__ B, int ldb, long strideB,
    float* __restrict__ C, int ldc, long strideC, long partStride,
    const float* __restrict__ res, const float* __restrict__ rbias,
    const float* __restrict__ alphap,
    int K, int ksplit)
{
    constexpr int BK  = 32;
    constexpr int LDS = 48;   // 96 B row stride (32B-multiple for WMMA alignment)

    __shared__ __align__(32) __nv_bfloat16 As[2][128][LDS];
    __shared__ __align__(32) __nv_bfloat16 Bs[2][128][LDS];

    const int tid  = threadIdx.x;
    const int wid  = tid >> 5;
    const int wm   = wid & 3;
    const int wn   = wid >> 2;

    const int b  = blockIdx.z / ksplit;
    const int sp = blockIdx.z % ksplit;
    const int klen = K / ksplit;
    const int kBeg = sp * klen;
    const int ntiles = klen / BK;

    const __nv_bfloat16* Ab = A + (long)b * strideA + (long)(blockIdx.y * 128) * lda;
    const __nv_bfloat16* Bb = B + (long)b * strideB + (long)(blockIdx.x * 128) * ldb;
    float* Cb = C + (long)b * strideC + (long)sp * partStride;
    const float* Rb = (MODE == 2) ? (res + (long)b * strideC) : nullptr;

    const int r0 = tid >> 2;          // 0..63
    const int c0 = tid & 3;           // 0..3

    auto load_stage = [&](int s, int k0) {
#pragma unroll
        for (int half = 0; half < 2; half++) {
            const int row = r0 + half * 64;
            cp_async16(smem_u32(&As[s][row][c0 * 8]),
                       Ab + (long)row * lda + k0 + c0 * 8);
            cp_async16(smem_u32(&Bs[s][row][c0 * 8]),
                       Bb + (long)row * ldb + k0 + c0 * 8);
        }
    };

    wmma::fragment<wmma::accumulator, 16, 16, 16, float> acc[2][4];
#pragma unroll
    for (int i = 0; i < 2; i++)
#pragma unroll
        for (int j = 0; j < 4; j++) wmma::fill_fragment(acc[i][j], 0.0f);

    load_stage(0, kBeg);
    CP_COMMIT();

    for (int kt = 0; kt < ntiles; kt++) {
        if (kt + 1 < ntiles) {
            load_stage((kt + 1) & 1, kBeg + (kt + 1) * BK);
            CP_COMMIT();
            CP_WAIT(1);
        } else {
            CP_WAIT(0);
        }
        __syncthreads();

        const int s = kt & 1;
#pragma unroll
        for (int ks = 0; ks < BK; ks += 16) {
            wmma::fragment<wmma::matrix_a, 16, 16, 16, __nv_bfloat16, wmma::row_major> af[2];
            wmma::fragment<wmma::matrix_b, 16, 16, 16, __nv_bfloat16, wmma::col_major> bf[4];
#pragma unroll
            for (int i = 0; i < 2; i++)
                wmma::load_matrix_sync(af[i], &As[s][wm * 32 + i * 16][ks], LDS);
#pragma unroll
            for (int j = 0; j < 4; j++)
                wmma::load_matrix_sync(bf[j], &Bs[s][wn * 64 + j * 16][ks], LDS);
#pragma unroll
            for (int i = 0; i < 2; i++)
#pragma unroll
                for (int j = 0; j < 4; j++)
                    wmma::mma_sync(acc[i][j], af[i], bf[j], acc[i][j]);
        }
        __syncthreads();
    }

    if (MODE == 0) {
#pragma unroll
        for (int i = 0; i < 2; i++) {
            const int row0 = blockIdx.y * 128 + wm * 32 + i * 16;
#pragma unroll
            for (int j = 0; j < 4; j++) {
                const int col0 = blockIdx.x * 128 + wn * 64 + j * 16;
                wmma::store_matrix_sync(&Cb[(long)row0 * ldc + col0], acc[i][j],
                                        ldc, wmma::mem_row_major);
            }
        }
    } else {
        // Fused residual epilogue via SMEM staging (reuse As; per-warp region).
        float* stg = reinterpret_cast<float*>(&As[0][0][0]) + wid * (16 * 18);
        const float alpha = *alphap;
        const int lane = tid & 31;
        const int r    = lane >> 1;
        const int cb   = (lane & 1) * 8;
#pragma unroll
        for (int i = 0; i < 2; i++) {
            const int row0 = blockIdx.y * 128 + wm * 32 + i * 16;
            const float bv = rbias[row0 + r];
#pragma unroll
            for (int j = 0; j < 4; j++) {
                const int col0 = blockIdx.x * 128 + wn * 64 + j * 16;
                wmma::store_matrix_sync(stg, acc[i][j], 18, wmma::mem_row_major);
                __syncwarp();
                const long off = (long)(row0 + r) * ldc + col0 + cb;
#pragma unroll
                for (int e = 0; e < 8; e++) {
                    const float v = stg[r * 18 + cb + e];
                    Cb[off + e] = Rb[off + e] + alpha * (v + bv);
                }
                __syncwarp();
            }
        }
    }
}

// ---------------------------------------------------------------------------
// fp32 [rows,cols] -> bf16 straight + bf16 transposed
// ---------------------------------------------------------------------------
__global__ __launch_bounds__(256) void convT_kernel(
    const float* __restrict__ X, __nv_bfloat16* __restrict__ Xbf,
    __nv_bfloat16* __restrict__ XT, int rows, int cols)
{
    __shared__ float t[32][33];
    const long bofs = (long)blockIdx.z * rows * cols;
    const int c0 = blockIdx.x * 32, r0 = blockIdx.y * 32;
    const int tx = threadIdx.x & 31, ty = threadIdx.x >> 5;
#pragma unroll
    for (int i = ty; i < 32; i += 8) {
        float v = X[bofs + (long)(r0 + i) * cols + c0 + tx];
        t[i][tx] = v;
        Xbf[bofs + (long)(r0 + i) * cols + c0 + tx] = __float2bfloat16(v);
    }
    __syncthreads();
#pragma unroll
    for (int i = ty; i < 32; i += 8)
        XT[bofs + (long)(c0 + i) * rows + r0 + tx] = __float2bfloat16(t[tx][i]);
}

__global__ __launch_bounds__(256) void convW_kernel(
    const float* __restrict__ W, __nv_bfloat16* __restrict__ Wb, int n)
{
    int i = blockIdx.x * 256 + threadIdx.x;
    if (i < n) Wb[i] = __float2bfloat16(W[i]);
}

__global__ void zeroS_kernel(float* S)
{
    int i = blockIdx.x * 256 + threadIdx.x;
    if (i < NB * 2 * NREG) S[i] = 0.f;
}

// ---------------------------------------------------------------------------
// Row softmax over 512 (+bias fold) with fused row-sum accumulation into S.
// One warp per pixel-row; 8 rows per block (all in the same batch).
// ---------------------------------------------------------------------------
__global__ __launch_bounds__(256) void softmax_rows_kernel(
    const float* __restrict__ L, const float* __restrict__ bias,
    __nv_bfloat16* __restrict__ PT, float* __restrict__ S, int which)
{
    __shared__ float sacc[NREG];
    const int tid = threadIdx.x;
    for (int i = tid; i < NREG; i += 256) sacc[i] = 0.f;
    __syncthreads();

    const long row = (long)blockIdx.x * 8 + (tid >> 5);
    const int lane = tid & 31;
    const float* rp = L + row * NREG;
    float v[16];
    float mx = -1e30f;
#pragma unroll
    for (int i = 0; i < 16; i++) {
        v[i] = rp[lane + i * 32] + bias[lane + i * 32];
        mx = fmaxf(mx, v[i]);
    }
#pragma unroll
    for (int o = 16; o > 0; o >>= 1) mx = fmaxf(mx, __shfl_xor_sync(0xffffffffu, mx, o));
    float s = 0.f;
#pragma unroll
    for (int i = 0; i < 16; i++) { v[i] = __expf(v[i] - mx); s += v[i]; }
#pragma unroll
    for (int o = 16; o > 0; o >>= 1) s += __shfl_xor_sync(0xffffffffu, s, o);
    const float inv = 1.f / s;
    __nv_bfloat16* pp = PT + row * NREG;
#pragma unroll
    for (int i = 0; i < 16; i++) {
        const float p = v[i] * inv;
        pp[lane + i * 32] = __float2bfloat16(p);
        atomicAdd(&sacc[lane + i * 32], p);
    }
    __syncthreads();

    const int b = (int)((blockIdx.x * 8) / NPIX);
    float* Sb = S + ((long)b * 2 + which) * NREG;
    for (int i = tid; i < NREG; i += 256) atomicAdd(&Sb[i], sacc[i]);
}

// ---------------------------------------------------------------------------
// bf16 transpose: PT [NPIX,512] -> P [512,NPIX] per batch
// ---------------------------------------------------------------------------
__global__ __launch_bounds__(256) void transpose_bf_kernel(
    const __nv_bfloat16* __restrict__ PT, __nv_bfloat16* __restrict__ P)
{
    __shared__ __nv_bfloat16 t[32][33];
    const long bi = (long)blockIdx.z * NPIX * NREG;
    const int j0 = blockIdx.x * 32, n0 = blockIdx.y * 32;
    const int tx = threadIdx.x & 31, ty = threadIdx.x >> 5;
#pragma unroll
    for (int i = ty; i < 32; i += 8)
        t[i][tx] = PT[bi + (long)(n0 + i) * NREG + j0 + tx];
    __syncthreads();
#pragma unroll
    for (int i = ty; i < 32; i += 8)
        P[bi + (long)(j0 + i) * NPIX + n0 + tx] = t[tx][i];
}

// ---------------------------------------------------------------------------
// Reduce KSPLIT_G partials
// ---------------------------------------------------------------------------
__global__ __launch_bounds__(256) void reduceG_kernel(
    const float* __restrict__ Gp, float* __restrict__ G, int n, long part)
{
    int i = blockIdx.x * 256 + threadIdx.x;
    if (i < n)
        G[i] = Gp[i] + Gp[i + part] + Gp[i + 2 * part] + Gp[i + 3 * part];
}

// ---------------------------------------------------------------------------
// Per-(b,h) region attention -> M (bf16)
// ---------------------------------------------------------------------------
__global__ __launch_bounds__(128) void region_attn_kernel(
    const float* __restrict__ G, const float* __restrict__ S,
    const float* __restrict__ Wq,  const float* __restrict__ bq,
    const float* __restrict__ Wkv, const float* __restrict__ bkv,
    const float* __restrict__ Wout,
    __nv_bfloat16* __restrict__ M)
{
    const int h = blockIdx.x, b = blockIdx.y;
    const float* Gt = G + ((long)b * 2 + 0) * NC * NREG;
    const float* Gs = G + ((long)b * 2 + 1) * NC * NREG;
    const float* Sq = S + ((long)b * 2 + 0) * NREG;
    const float* Sk = S + ((long)b * 2 + 1) * NREG;

    __shared__ float qr[32][64];
    __shared__ float kr[32][64];
    __shared__ float vr[32][64];
    __shared__ float attn[64][65];

    const int tid = threadIdx.x;

    for (int idx = tid; idx < 32 * 64; idx += 128) {
        const int d = idx >> 6, r = idx & 63;
        const int row = h * 32 + d, j = h * 64 + r;
        float s0 = 0.f, s1 = 0.f;
        for (int c = 0; c < 256; c += 2) {
            s0 += Wq[row * 256 + c + 0] * Gt[(c + 0) * NREG + j];
            s1 += Wq[row * 256 + c + 1] * Gt[(c + 1) * NREG + j];
        }
        qr[d][r] = s0 + s1 + bq[row] * Sq[j];
    }
    for (int idx = tid; idx < 32 * 64; idx += 128) {
        const int d = idx >> 6, r = idx & 63;
        const int rk = h * 64 + d, rv = h * 64 + 32 + d, j = h * 64 + r;
        float sk = 0.f, sv = 0.f;
        for (int c = 0; c < 256; c++) {
            const float g = Gs[c * NREG + j];
            sk += Wkv[rk * 256 + c] * g;
            sv += Wkv[rv * 256 + c] * g;
        }
        kr[d][r] = sk + bkv[rk] * Sk[j];
        vr[d][r] = sv + bkv[rv] * Sk[j];
    }
    __syncthreads();

    const float scale = rsqrtf((float)NHD);
    for (int idx = tid; idx < 64 * 64; idx += 128) {
        const int qi = idx >> 6, ki = idx & 63;
        float s = 0.f;
#pragma unroll
        for (int d = 0; d < 32; d++) s += qr[d][qi] * kr[d][ki];
        attn[qi][ki] = s * scale;
    }
    __syncthreads();

    if (tid < 64) {
        float mx = -1e30f;
        for (int k = 0; k < 64; k++) mx = fmaxf(mx, attn[tid][k]);
        float s = 0.f;
        for (int k = 0; k < 64; k++) {
            const float e = __expf(attn[tid][k] - mx);
            attn[tid][k] = e;
            s += e;
        }
        const float inv = 1.f / s;
        for (int k = 0; k < 64; k++) attn[tid][k] *= inv;
    }
    __syncthreads();

    for (int idx = tid; idx < 32 * 64; idx += 128) {
        const int d = idx >> 6, qi = idx & 63;
        float s = 0.f;
#pragma unroll
        for (int k = 0; k < 64; k++) s += vr[d][k] * attn[qi][k];
        qr[d][qi] = s;
    }
    __syncthreads();

    for (int idx = tid; idx < 256 * 64; idx += 128) {
        const int c = idx >> 6, r = idx & 63;
        float s = 0.f;
#pragma unroll
        for (int d = 0; d < 32; d++) s += Wout[c * 256 + h * 32 + d] * qr[d][r];
        M[((long)b * NC + c) * NREG + h * 64 + r] = __float2bfloat16(s);
    }
}

// ---------------------------------------------------------------------------
// Launch
// ---------------------------------------------------------------------------
extern "C" void kernel_launch(void* const* d_in, const int* in_sizes, int n_in,
                              void* d_out, int out_size)
{
    const float* src  = (const float*)d_in[0];
    const float* tgt  = (const float*)d_in[1];
    const float* Wq   = (const float*)d_in[2];
    const float* bq   = (const float*)d_in[3];
    const float* Wkv  = (const float*)d_in[4];
    const float* bkv  = (const float*)d_in[5];
    const float* Wrq  = (const float*)d_in[6];
    const float* brq  = (const float*)d_in[7];
    const float* Wrk  = (const float*)d_in[8];
    const float* brk  = (const float*)d_in[9];
    const float* Wout = (const float*)d_in[10];
    const float* bout = (const float*)d_in[11];
    const float* alpha = (const float*)d_in[12];
    float* out = (float*)d_out;

    float *L, *Gp, *G, *S;
    __nv_bfloat16 *PqT, *PkT, *Pq, *Pk, *tgt_bf, *src_bf, *tgtT, *srcT, *Wrq_bf, *Wrk_bf, *Mbf;
    cudaGetSymbolAddress((void**)&L,      g_L);
    cudaGetSymbolAddress((void**)&PqT,    g_PqT);
    cudaGetSymbolAddress((void**)&PkT,    g_PkT);
    cudaGetSymbolAddress((void**)&Pq,     g_Pq);
    cudaGetSymbolAddress((void**)&Pk,     g_Pk);
    cudaGetSymbolAddress((void**)&tgt_bf, g_tgt_bf);
    cudaGetSymbolAddress((void**)&src_bf, g_src_bf);
    cudaGetSymbolAddress((void**)&tgtT,   g_tgtT_bf);
    cudaGetSymbolAddress((void**)&srcT,   g_srcT_bf);
    cudaGetSymbolAddress((void**)&Wrq_bf, g_Wrq_bf);
    cudaGetSymbolAddress((void**)&Wrk_bf, g_Wrk_bf);
    cudaGetSymbolAddress((void**)&Gp,     g_Gp);
    cudaGetSymbolAddress((void**)&G,      g_G);
    cudaGetSymbolAddress((void**)&S,      g_S);
    cudaGetSymbolAddress((void**)&Mbf,    g_Mbf);

    const long GTOT = (long)NB * 2 * NC * NREG;

    // 0) conversions + S zero
    convT_kernel<<<dim3(NPIX / 32, NC / 32, NB), 256>>>(tgt, tgt_bf, tgtT, NC, NPIX);
    convT_kernel<<<dim3(NPIX / 32, NC / 32, NB), 256>>>(src, src_bf, srcT, NC, NPIX);
    convW_kernel<<<(NREG * NC + 255) / 256, 256>>>(Wrq, Wrq_bf, NREG * NC);
    convW_kernel<<<(NREG * NC + 255) / 256, 256>>>(Wrk, Wrk_bf, NREG * NC);
    zeroS_kernel<<<(NB * 2 * NREG + 255) / 256, 256>>>(S);

    // 1q) raw Lq[n,j] = tgtT . Wrq^T ; softmax(+brq, fused rowsum) -> PqT ; transpose
    gemm_wmma_kernel<0><<<dim3(NREG / 128, NPIX / 128, NB), 256>>>(
        tgtT, NC, (long)NPIX * NC, Wrq_bf, NC, 0,
        L, NREG, (long)NPIX * NREG, 0, nullptr, nullptr, nullptr, NC, 1);
    softmax_rows_kernel<<<NB * NPIX / 8, 256>>>(L, brq, PqT, S, 0);
    transpose_bf_kernel<<<dim3(NREG / 32, NPIX / 32, NB), 256>>>(PqT, Pq);

    // 1k) same for k
    gemm_wmma_kernel<0><<<dim3(NREG / 128, NPIX / 128, NB), 256>>>(
        srcT, NC, (long)NPIX * NC, Wrk_bf, NC, 0,
        L, NREG, (long)NPIX * NREG, 0, nullptr, nullptr, nullptr, NC, 1);
    softmax_rows_kernel<<<NB * NPIX / 8, 256>>>(L, brk, PkT, S, 1);
    transpose_bf_kernel<<<dim3(NREG / 32, NPIX / 32, NB), 256>>>(PkT, Pk);

    // 2) G matrices: NT GEMMs on P; K-split partials, reduce
    gemm_wmma_kernel<0><<<dim3(NREG / 128, NC / 128, NB * KSPLIT_G), 256>>>(
        tgt_bf, NPIX, (long)NC * NPIX, Pq, NPIX, (long)NREG * NPIX,
        Gp, NREG, (long)2 * NC * NREG, GTOT, nullptr, nullptr, nullptr, NPIX, KSPLIT_G);
    gemm_wmma_kernel<0><<<dim3(NREG / 128, NC / 128, NB * KSPLIT_G), 256>>>(
        src_bf, NPIX, (long)NC * NPIX, Pk, NPIX, (long)NREG * NPIX,
        Gp + (long)NC * NREG, NREG, (long)2 * NC * NREG, GTOT, nullptr, nullptr, nullptr,
        NPIX, KSPLIT_G);
    reduceG_kernel<<<(int)((GTOT + 255) / 256), 256>>>(Gp, G, (int)GTOT, GTOT);

    // 3) small attention -> M (bf16)
    region_attn_kernel<<<dim3(NHEAD, NB), 128>>>(G, S, Wq, bq, Wkv, bkv, Wout, Mbf);

    // 4) out = tgt + alpha*(M . Pq + bout)  -- fused epilogue, B = PqT (NT form)
    gemm_wmma_kernel<2><<<dim3(NPIX / 128, NC / 128, NB), 256>>>(
        Mbf, NREG, (long)NC * NREG, PqT, NREG, (long)NPIX * NREG,
        out, NPIX, (long)NC * NPIX, 0, tgt, bout, alpha, NREG, 1);

    (void)in_sizes; (void)n_in; (void)out_size;
}

// round 11
// speedup vs baseline: 1.1342x; 1.1342x over previous
#include <cuda_runtime.h>
#include <cuda_bf16.h>
#include <mma.h>
#include <cstdint>

using namespace nvcuda;

// ---------------------------------------------------------------------------
// Problem constants
// ---------------------------------------------------------------------------
#define NB    8
#define NPIX  9216     // 96*96
#define NREG  512      // R*HEADS
#define NC    256      // channels / E
#define NHEAD 8
#define NHD   32
#define KSPLIT_G 4

// ---------------------------------------------------------------------------
// Scratch (device globals)
// ---------------------------------------------------------------------------
__device__ float         g_L   [(size_t)NB * NPIX * NREG];   // raw logits / raw final
__device__ __nv_bfloat16 g_PqT [(size_t)NB * NPIX * NREG];
__device__ __nv_bfloat16 g_PkT [(size_t)NB * NPIX * NREG];
__device__ __nv_bfloat16 g_tgt_bf [(size_t)NB * NC * NPIX];
__device__ __nv_bfloat16 g_src_bf [(size_t)NB * NC * NPIX];
__device__ __nv_bfloat16 g_tgtT_bf[(size_t)NB * NPIX * NC];
__device__ __nv_bfloat16 g_srcT_bf[(size_t)NB * NPIX * NC];
__device__ __nv_bfloat16 g_Wrq_bf[NREG * NC];
__device__ __nv_bfloat16 g_Wrk_bf[NREG * NC];
__device__ float         g_Gp  [(size_t)KSPLIT_G * NB * 2 * NC * NREG];
__device__ float         g_G   [(size_t)NB * 2 * NC * NREG];
__device__ float         g_S   [(size_t)NB * 2 * NREG];
__device__ __nv_bfloat16 g_Mbf [(size_t)NB * NC * NREG];

// ---------------------------------------------------------------------------
// cp.async helpers
// ---------------------------------------------------------------------------
__device__ __forceinline__ uint32_t smem_u32(const void* p) {
    uint32_t a;
    asm("{ .reg .u64 t; cvta.to.shared.u64 t, %1; cvt.u32.u64 %0, t; }"
        : "=r"(a) : "l"(p));
    return a;
}
__device__ __forceinline__ void cp_async16(uint32_t dst, const void* src) {
    asm volatile("cp.async.cg.shared.global [%0], [%1], 16;\n" :: "r"(dst), "l"(src));
}
#define CP_COMMIT()  asm volatile("cp.async.commit_group;\n" ::: "memory")
#define CP_WAIT(n)   asm volatile("cp.async.wait_group %0;\n" :: "n"(n) : "memory")

// ---------------------------------------------------------------------------
// WMMA bf16 GEMM, CTA tile 128x128, BK=32, 8 warps (4x2), warp tile 32x64.
// BNN=0: B is K-major [n][k]   (NT form, col_major b-frags).
// BNN=1: B is N-major [k][n]   (NN form, row_major b-frags) -- reads PT directly.
// Raw fp32 store; optional ksplit partial offset partStride.
// ---------------------------------------------------------------------------
template<int BNN>
__global__ __launch_bounds__(256) void gemm_wmma_kernel(
    const __nv_bfloat16* __restrict__ A, int lda, long strideA,
    const __nv_bfloat16* __restrict__ B, int ldb, long strideB,
    float* __restrict__ C, int ldc, long strideC, long partStride,
    int K, int ksplit)
{
    constexpr int BK  = 32;
    constexpr int LDSA = 48;                    // 96 B rows
    constexpr int BROWS = BNN ? 32  : 128;
    constexpr int BCOLS = BNN ? 144 : 48;       // 288 B / 96 B rows

    __shared__ __align__(32) __nv_bfloat16 As[2][128][LDSA];
    __shared__ __align__(32) __nv_bfloat16 Bs[2][BROWS][BCOLS];

    const int tid  = threadIdx.x;
    const int wid  = tid >> 5;
    const int wm   = wid & 3;
    const int wn   = wid >> 2;

    const int b  = blockIdx.z / ksplit;
    const int sp = blockIdx.z % ksplit;
    const int klen = K / ksplit;
    const int kBeg = sp * klen;
    const int ntiles = klen / BK;

    const __nv_bfloat16* Ab = A + (long)b * strideA + (long)(blockIdx.y * 128) * lda;
    const __nv_bfloat16* Bb;
    if (BNN) Bb = B + (long)b * strideB + blockIdx.x * 128;               // col offset
    else     Bb = B + (long)b * strideB + (long)(blockIdx.x * 128) * ldb; // row offset
    float* Cb = C + (long)b * strideC + (long)sp * partStride;

    const int r0 = tid >> 2;          // 0..63
    const int c0 = tid & 3;           // 0..3

    auto load_stage = [&](int s, int k0) {
#pragma unroll
        for (int half = 0; half < 2; half++) {
            const int row = r0 + half * 64;
            cp_async16(smem_u32(&As[s][row][c0 * 8]),
                       Ab + (long)row * lda + k0 + c0 * 8);
        }
        if (BNN) {
#pragma unroll
            for (int h = 0; h < 2; h++) {
                const int ch = tid + h * 256;       // 512 chunks: 32 rows x 16
                const int row = ch >> 4;
                const int cc  = ch & 15;
                cp_async16(smem_u32(&Bs[s][row][cc * 8]),
                           Bb + (long)(k0 + row) * ldb + cc * 8);
            }
        } else {
#pragma unroll
            for (int half = 0; half < 2; half++) {
                const int row = r0 + half * 64;
                cp_async16(smem_u32(&Bs[s][row][c0 * 8]),
                           Bb + (long)row * ldb + k0 + c0 * 8);
            }
        }
    };

    wmma::fragment<wmma::accumulator, 16, 16, 16, float> acc[2][4];
#pragma unroll
    for (int i = 0; i < 2; i++)
#pragma unroll
        for (int j = 0; j < 4; j++) wmma::fill_fragment(acc[i][j], 0.0f);

    load_stage(0, kBeg);
    CP_COMMIT();

    for (int kt = 0; kt < ntiles; kt++) {
        if (kt + 1 < ntiles) {
            load_stage((kt + 1) & 1, kBeg + (kt + 1) * BK);
            CP_COMMIT();
            CP_WAIT(1);
        } else {
            CP_WAIT(0);
        }
        __syncthreads();

        const int s = kt & 1;
#pragma unroll
        for (int ks = 0; ks < BK; ks += 16) {
            wmma::fragment<wmma::matrix_a, 16, 16, 16, __nv_bfloat16, wmma::row_major> af[2];
#pragma unroll
            for (int i = 0; i < 2; i++)
                wmma::load_matrix_sync(af[i], &As[s][wm * 32 + i * 16][ks], LDSA);
            if (BNN) {
                wmma::fragment<wmma::matrix_b, 16, 16, 16, __nv_bfloat16, wmma::row_major> bf[4];
#pragma unroll
                for (int j = 0; j < 4; j++)
                    wmma::load_matrix_sync(bf[j], &Bs[s][ks][wn * 64 + j * 16], BCOLS);
#pragma unroll
                for (int i = 0; i < 2; i++)
#pragma unroll
                    for (int j = 0; j < 4; j++)
                        wmma::mma_sync(acc[i][j], af[i], bf[j], acc[i][j]);
            } else {
                wmma::fragment<wmma::matrix_b, 16, 16, 16, __nv_bfloat16, wmma::col_major> bf[4];
#pragma unroll
                for (int j = 0; j < 4; j++)
                    wmma::load_matrix_sync(bf[j], &Bs[s][wn * 64 + j * 16][ks], BCOLS);
#pragma unroll
                for (int i = 0; i < 2; i++)
#pragma unroll
                    for (int j = 0; j < 4; j++)
                        wmma::mma_sync(acc[i][j], af[i], bf[j], acc[i][j]);
            }
        }
        __syncthreads();
    }

#pragma unroll
    for (int i = 0; i < 2; i++) {
        const int row0 = blockIdx.y * 128 + wm * 32 + i * 16;
#pragma unroll
        for (int j = 0; j < 4; j++) {
            const int col0 = blockIdx.x * 128 + wn * 64 + j * 16;
            wmma::store_matrix_sync(&Cb[(long)row0 * ldc + col0], acc[i][j],
                                    ldc, wmma::mem_row_major);
        }
    }
}

// ---------------------------------------------------------------------------
// fp32 [rows,cols] -> bf16 straight + bf16 transposed
// ---------------------------------------------------------------------------
__global__ __launch_bounds__(256) void convT_kernel(
    const float* __restrict__ X, __nv_bfloat16* __restrict__ Xbf,
    __nv_bfloat16* __restrict__ XT, int rows, int cols)
{
    __shared__ float t[32][33];
    const long bofs = (long)blockIdx.z * rows * cols;
    const int c0 = blockIdx.x * 32, r0 = blockIdx.y * 32;
    const int tx = threadIdx.x & 31, ty = threadIdx.x >> 5;
#pragma unroll
    for (int i = ty; i < 32; i += 8) {
        float v = X[bofs + (long)(r0 + i) * cols + c0 + tx];
        t[i][tx] = v;
        Xbf[bofs + (long)(r0 + i) * cols + c0 + tx] = __float2bfloat16(v);
    }
    __syncthreads();
#pragma unroll
    for (int i = ty; i < 32; i += 8)
        XT[bofs + (long)(c0 + i) * rows + r0 + tx] = __float2bfloat16(t[tx][i]);
}

__global__ __launch_bounds__(256) void convW_kernel(
    const float* __restrict__ W, __nv_bfloat16* __restrict__ Wb, int n)
{
    int i = blockIdx.x * 256 + threadIdx.x;
    if (i < n) Wb[i] = __float2bfloat16(W[i]);
}

__global__ void zeroS_kernel(float* S)
{
    int i = blockIdx.x * 256 + threadIdx.x;
    if (i < NB * 2 * NREG) S[i] = 0.f;
}

// ---------------------------------------------------------------------------
// Row softmax over 512 (+bias fold): raw logits L -> P^T bf16. One warp/row.
// (R7 version: no atomics, no fused rowsum)
// ---------------------------------------------------------------------------
__global__ __launch_bounds__(256) void softmax_rows_kernel(
    const float* __restrict__ L, const float* __restrict__ bias,
    __nv_bfloat16* __restrict__ PT)
{
    const long row = (long)blockIdx.x * 8 + (threadIdx.x >> 5);
    const int lane = threadIdx.x & 31;
    const float* rp = L + row * NREG;
    float v[16];
    float mx = -1e30f;
#pragma unroll
    for (int i = 0; i < 16; i++) {
        v[i] = rp[lane + i * 32] + bias[lane + i * 32];
        mx = fmaxf(mx, v[i]);
    }
#pragma unroll
    for (int o = 16; o > 0; o >>= 1) mx = fmaxf(mx, __shfl_xor_sync(0xffffffffu, mx, o));
    float s = 0.f;
#pragma unroll
    for (int i = 0; i < 16; i++) { v[i] = __expf(v[i] - mx); s += v[i]; }
#pragma unroll
    for (int o = 16; o > 0; o >>= 1) s += __shfl_xor_sync(0xffffffffu, s, o);
    const float inv = 1.f / s;
    __nv_bfloat16* pp = PT + row * NREG;
#pragma unroll
    for (int i = 0; i < 16; i++) pp[lane + i * 32] = __float2bfloat16(v[i] * inv);
}

// ---------------------------------------------------------------------------
// Column sums of PT: S[b][which][j] += sum_n PT[b][n][j].
// Coalesced: thread owns cols tid and tid+256 in registers, loops 64 rows.
// grid (NPIX/64, NB). 2 global atomics per thread at the end.
// ---------------------------------------------------------------------------
__global__ __launch_bounds__(256) void rowsumT_kernel(
    const __nv_bfloat16* __restrict__ PT, float* __restrict__ S, int which)
{
    const int b = blockIdx.y;
    const int tid = threadIdx.x;
    const __nv_bfloat16* base =
        PT + (long)b * NPIX * NREG + (long)blockIdx.x * 64 * NREG;
    float v0 = 0.f, v1 = 0.f;
#pragma unroll 4
    for (int r = 0; r < 64; r++) {
        v0 += __bfloat162float(base[(long)r * NREG + tid]);
        v1 += __bfloat162float(base[(long)r * NREG + tid + 256]);
    }
    float* Sb = S + ((long)b * 2 + which) * NREG;
    atomicAdd(&Sb[tid], v0);
    atomicAdd(&Sb[tid + 256], v1);
}

// ---------------------------------------------------------------------------
// Reduce KSPLIT_G partials
// ---------------------------------------------------------------------------
__global__ __launch_bounds__(256) void reduceG_kernel(
    const float* __restrict__ Gp, float* __restrict__ G, int n, long part)
{
    int i = blockIdx.x * 256 + threadIdx.x;
    if (i < n)
        G[i] = Gp[i] + Gp[i + part] + Gp[i + 2 * part] + Gp[i + 3 * part];
}

// ---------------------------------------------------------------------------
// Final elementwise: out = tgt + alpha*(raw + bout[c]); float4-vectorized.
// ---------------------------------------------------------------------------
__global__ __launch_bounds__(256) void final_ep_kernel(
    const float* __restrict__ raw, const float* __restrict__ tgt,
    const float* __restrict__ bout, const float* __restrict__ alphap,
    float* __restrict__ out)
{
    const long i4 = (long)blockIdx.x * 256 + threadIdx.x;
    const long base = i4 * 4;
    const int c = (int)((base / NPIX) % NC);
    const float alpha = *alphap;
    const float bv = bout[c];
    float4 r = *(const float4*)(raw + base);
    float4 t = *(const float4*)(tgt + base);
    float4 o;
    o.x = t.x + alpha * (r.x + bv);
    o.y = t.y + alpha * (r.y + bv);
    o.z = t.z + alpha * (r.z + bv);
    o.w = t.w + alpha * (r.w + bv);
    *(float4*)(out + base) = o;
}

// ---------------------------------------------------------------------------
// Per-(b,h) region attention -> M (bf16)
// ---------------------------------------------------------------------------
__global__ __launch_bounds__(128) void region_attn_kernel(
    const float* __restrict__ G, const float* __restrict__ S,
    const float* __restrict__ Wq,  const float* __restrict__ bq,
    const float* __restrict__ Wkv, const float* __restrict__ bkv,
    const float* __restrict__ Wout,
    __nv_bfloat16* __restrict__ M)
{
    const int h = blockIdx.x, b = blockIdx.y;
    const float* Gt = G + ((long)b * 2 + 0) * NC * NREG;
    const float* Gs = G + ((long)b * 2 + 1) * NC * NREG;
    const float* Sq = S + ((long)b * 2 + 0) * NREG;
    const float* Sk = S + ((long)b * 2 + 1) * NREG;

    __shared__ float qr[32][64];
    __shared__ float kr[32][64];
    __shared__ float vr[32][64];
    __shared__ float attn[64][65];

    const int tid = threadIdx.x;

    for (int idx = tid; idx < 32 * 64; idx += 128) {
        const int d = idx >> 6, r = idx & 63;
        const int row = h * 32 + d, j = h * 64 + r;
        float s0 = 0.f, s1 = 0.f;
        for (int c = 0; c < 256; c += 2) {
            s0 += Wq[row * 256 + c + 0] * Gt[(c + 0) * NREG + j];
            s1 += Wq[row * 256 + c + 1] * Gt[(c + 1) * NREG + j];
        }
        qr[d][r] = s0 + s1 + bq[row] * Sq[j];
    }
    for (int idx = tid; idx < 32 * 64; idx += 128) {
        const int d = idx >> 6, r = idx & 63;
        const int rk = h * 64 + d, rv = h * 64 + 32 + d, j = h * 64 + r;
        float sk = 0.f, sv = 0.f;
        for (int c = 0; c < 256; c++) {
            const float g = Gs[c * NREG + j];
            sk += Wkv[rk * 256 + c] * g;
            sv += Wkv[rv * 256 + c] * g;
        }
        kr[d][r] = sk + bkv[rk] * Sk[j];
        vr[d][r] = sv + bkv[rv] * Sk[j];
    }
    __syncthreads();

    const float scale = rsqrtf((float)NHD);
    for (int idx = tid; idx < 64 * 64; idx += 128) {
        const int qi = idx >> 6, ki = idx & 63;
        float s = 0.f;
#pragma unroll
        for (int d = 0; d < 32; d++) s += qr[d][qi] * kr[d][ki];
        attn[qi][ki] = s * scale;
    }
    __syncthreads();

    if (tid < 64) {
        float mx = -1e30f;
        for (int k = 0; k < 64; k++) mx = fmaxf(mx, attn[tid][k]);
        float s = 0.f;
        for (int k = 0; k < 64; k++) {
            const float e = __expf(attn[tid][k] - mx);
            attn[tid][k] = e;
            s += e;
        }
        const float inv = 1.f / s;
        for (int k = 0; k < 64; k++) attn[tid][k] *= inv;
    }
    __syncthreads();

    for (int idx = tid; idx < 32 * 64; idx += 128) {
        const int d = idx >> 6, qi = idx & 63;
        float s = 0.f;
#pragma unroll
        for (int k = 0; k < 64; k++) s += vr[d][k] * attn[qi][k];
        qr[d][qi] = s;
    }
    __syncthreads();

    for (int idx = tid; idx < 256 * 64; idx += 128) {
        const int c = idx >> 6, r = idx & 63;
        float s = 0.f;
#pragma unroll
        for (int d = 0; d < 32; d++) s += Wout[c * 256 + h * 32 + d] * qr[d][r];
        M[((long)b * NC + c) * NREG + h * 64 + r] = __float2bfloat16(s);
    }
}

// ---------------------------------------------------------------------------
// Launch
// ---------------------------------------------------------------------------
extern "C" void kernel_launch(void* const* d_in, const int* in_sizes, int n_in,
                              void* d_out, int out_size)
{
    const float* src  = (const float*)d_in[0];
    const float* tgt  = (const float*)d_in[1];
    const float* Wq   = (const float*)d_in[2];
    const float* bq   = (const float*)d_in[3];
    const float* Wkv  = (const float*)d_in[4];
    const float* bkv  = (const float*)d_in[5];
    const float* Wrq  = (const float*)d_in[6];
    const float* brq  = (const float*)d_in[7];
    const float* Wrk  = (const float*)d_in[8];
    const float* brk  = (const float*)d_in[9];
    const float* Wout = (const float*)d_in[10];
    const float* bout = (const float*)d_in[11];
    const float* alpha = (const float*)d_in[12];
    float* out = (float*)d_out;

    float *L, *Gp, *G, *S;
    __nv_bfloat16 *PqT, *PkT, *tgt_bf, *src_bf, *tgtT, *srcT, *Wrq_bf, *Wrk_bf, *Mbf;
    cudaGetSymbolAddress((void**)&L,      g_L);
    cudaGetSymbolAddress((void**)&PqT,    g_PqT);
    cudaGetSymbolAddress((void**)&PkT,    g_PkT);
    cudaGetSymbolAddress((void**)&tgt_bf, g_tgt_bf);
    cudaGetSymbolAddress((void**)&src_bf, g_src_bf);
    cudaGetSymbolAddress((void**)&tgtT,   g_tgtT_bf);
    cudaGetSymbolAddress((void**)&srcT,   g_srcT_bf);
    cudaGetSymbolAddress((void**)&Wrq_bf, g_Wrq_bf);
    cudaGetSymbolAddress((void**)&Wrk_bf, g_Wrk_bf);
    cudaGetSymbolAddress((void**)&Gp,     g_Gp);
    cudaGetSymbolAddress((void**)&G,      g_G);
    cudaGetSymbolAddress((void**)&S,      g_S);
    cudaGetSymbolAddress((void**)&Mbf,    g_Mbf);

    const long GTOT = (long)NB * 2 * NC * NREG;

    // 0) conversions + S zero
    convT_kernel<<<dim3(NPIX / 32, NC / 32, NB), 256>>>(tgt, tgt_bf, tgtT, NC, NPIX);
    convT_kernel<<<dim3(NPIX / 32, NC / 32, NB), 256>>>(src, src_bf, srcT, NC, NPIX);
    convW_kernel<<<(NREG * NC + 255) / 256, 256>>>(Wrq, Wrq_bf, NREG * NC);
    convW_kernel<<<(NREG * NC + 255) / 256, 256>>>(Wrk, Wrk_bf, NREG * NC);
    zeroS_kernel<<<(NB * 2 * NREG + 255) / 256, 256>>>(S);

    // 1q) raw Lq = tgtT . Wrq^T ; softmax(+brq) -> PqT ; coalesced column-sum
    gemm_wmma_kernel<0><<<dim3(NREG / 128, NPIX / 128, NB), 256>>>(
        tgtT, NC, (long)NPIX * NC, Wrq_bf, NC, 0,
        L, NREG, (long)NPIX * NREG, 0, NC, 1);
    softmax_rows_kernel<<<NB * NPIX / 8, 256>>>(L, brq, PqT);
    rowsumT_kernel<<<dim3(NPIX / 64, NB), 256>>>(PqT, S, 0);

    // 1k) same for k
    gemm_wmma_kernel<0><<<dim3(NREG / 128, NPIX / 128, NB), 256>>>(
        srcT, NC, (long)NPIX * NC, Wrk_bf, NC, 0,
        L, NREG, (long)NPIX * NREG, 0, NC, 1);
    softmax_rows_kernel<<<NB * NPIX / 8, 256>>>(L, brk, PkT);
    rowsumT_kernel<<<dim3(NPIX / 64, NB), 256>>>(PkT, S, 1);

    // 2) G matrices: NN GEMMs reading PT directly; K-split partials, reduce
    gemm_wmma_kernel<1><<<dim3(NREG / 128, NC / 128, NB * KSPLIT_G), 256>>>(
        tgt_bf, NPIX, (long)NC * NPIX, PqT, NREG, (long)NPIX * NREG,
        Gp, NREG, (long)2 * NC * NREG, GTOT, NPIX, KSPLIT_G);
    gemm_wmma_kernel<1><<<dim3(NREG / 128, NC / 128, NB * KSPLIT_G), 256>>>(
        src_bf, NPIX, (long)NC * NPIX, PkT, NREG, (long)NPIX * NREG,
        Gp + (long)NC * NREG, NREG, (long)2 * NC * NREG, GTOT, NPIX, KSPLIT_G);
    reduceG_kernel<<<(int)((GTOT + 255) / 256), 256>>>(Gp, G, (int)GTOT, GTOT);

    // 3) small attention -> M (bf16)
    region_attn_kernel<<<dim3(NHEAD, NB), 128>>>(G, S, Wq, bq, Wkv, bkv, Wout, Mbf);

    // 4) raw final = M . Pq (B = PqT, NT form), then coalesced residual pass
    gemm_wmma_kernel<0><<<dim3(NPIX / 128, NC / 128, NB), 256>>>(
        Mbf, NREG, (long)NC * NREG, PqT, NREG, (long)NPIX * NREG,
        L, NPIX, (long)NC * NPIX, 0, NREG, 1);
    final_ep_kernel<<<(int)((long)NB * NC * NPIX / 4 / 256), 256>>>(
        L, tgt, bout, alpha, out);

    (void)in_sizes; (void)n_in; (void)out_size;
}

// round 15
// speedup vs baseline: 1.1533x; 1.0168x over previous
#include <cuda_runtime.h>
#include <cuda_bf16.h>
#include <mma.h>
#include <cstdint>

using namespace nvcuda;

// ---------------------------------------------------------------------------
// Problem constants
// ---------------------------------------------------------------------------
#define NB    8
#define NPIX  9216     // 96*96
#define NREG  512      // R*HEADS
#define NC    256      // channels / E
#define NHEAD 8
#define NHD   32
#define KSPLIT_G 4

// ---------------------------------------------------------------------------
// Scratch (device globals)
// ---------------------------------------------------------------------------
__device__ __nv_bfloat16 g_Lbf [(size_t)NB * NPIX * NREG];   // bf16 logits / bf16 final raw
__device__ __nv_bfloat16 g_PqT [(size_t)NB * NPIX * NREG];
__device__ __nv_bfloat16 g_PkT [(size_t)NB * NPIX * NREG];
__device__ __nv_bfloat16 g_tgt_bf [(size_t)NB * NC * NPIX];
__device__ __nv_bfloat16 g_src_bf [(size_t)NB * NC * NPIX];
__device__ __nv_bfloat16 g_tgtT_bf[(size_t)NB * NPIX * NC];
__device__ __nv_bfloat16 g_srcT_bf[(size_t)NB * NPIX * NC];
__device__ __nv_bfloat16 g_Wrq_bf[NREG * NC];
__device__ __nv_bfloat16 g_Wrk_bf[NREG * NC];
__device__ float         g_Gp  [(size_t)KSPLIT_G * NB * 2 * NC * NREG];
__device__ float         g_G   [(size_t)NB * 2 * NC * NREG];
__device__ float         g_S   [(size_t)NB * 2 * NREG];
__device__ __nv_bfloat16 g_Mbf [(size_t)NB * NC * NREG];

// ---------------------------------------------------------------------------
// cp.async helpers
// ---------------------------------------------------------------------------
__device__ __forceinline__ uint32_t smem_u32(const void* p) {
    uint32_t a;
    asm("{ .reg .u64 t; cvta.to.shared.u64 t, %1; cvt.u32.u64 %0, t; }"
        : "=r"(a) : "l"(p));
    return a;
}
__device__ __forceinline__ void cp_async16(uint32_t dst, const void* src) {
    asm volatile("cp.async.cg.shared.global [%0], [%1], 16;\n" :: "r"(dst), "l"(src));
}
#define CP_COMMIT()  asm volatile("cp.async.commit_group;\n" ::: "memory")
#define CP_WAIT(n)   asm volatile("cp.async.wait_group %0;\n" :: "n"(n) : "memory")

// ---------------------------------------------------------------------------
// WMMA bf16 GEMM, CTA tile 128x128, BK=32, 8 warps (4x2), warp tile 32x64.
// BNN=0: B is K-major [n][k]   (NT form, col_major b-frags).
// BNN=1: B is N-major [k][n]   (NN form, row_major b-frags) -- reads PT directly.
// OUTBF=0: raw fp32 store (+optional ksplit partial offset partStride).
// OUTBF=1: bf16 store via SMEM staging, coalesced 128B row writes.
// ---------------------------------------------------------------------------
template<int BNN, int OUTBF>
__global__ __launch_bounds__(256) void gemm_wmma_kernel(
    const __nv_bfloat16* __restrict__ A, int lda, long strideA,
    const __nv_bfloat16* __restrict__ B, int ldb, long strideB,
    void* __restrict__ Cv, int ldc, long strideC, long partStride,
    int K, int ksplit)
{
    constexpr int BK  = 32;
    constexpr int LDSA = 48;                    // 96 B rows
    constexpr int BROWS = BNN ? 32  : 128;
    constexpr int BCOLS = BNN ? 144 : 48;       // 288 B / 96 B rows

    __shared__ __align__(32) __nv_bfloat16 As[2][128][LDSA];
    __shared__ __align__(32) __nv_bfloat16 Bs[2][BROWS][BCOLS];

    const int tid  = threadIdx.x;
    const int wid  = tid >> 5;
    const int wm   = wid & 3;
    const int wn   = wid >> 2;

    const int b  = blockIdx.z / ksplit;
    const int sp = blockIdx.z % ksplit;
    const int klen = K / ksplit;
    const int kBeg = sp * klen;
    const int ntiles = klen / BK;

    const __nv_bfloat16* Ab = A + (long)b * strideA + (long)(blockIdx.y * 128) * lda;
    const __nv_bfloat16* Bb;
    if (BNN) Bb = B + (long)b * strideB + blockIdx.x * 128;               // col offset
    else     Bb = B + (long)b * strideB + (long)(blockIdx.x * 128) * ldb; // row offset

    const int r0 = tid >> 2;          // 0..63
    const int c0 = tid & 3;           // 0..3

    auto load_stage = [&](int s, int k0) {
#pragma unroll
        for (int half = 0; half < 2; half++) {
            const int row = r0 + half * 64;
            cp_async16(smem_u32(&As[s][row][c0 * 8]),
                       Ab + (long)row * lda + k0 + c0 * 8);
        }
        if (BNN) {
#pragma unroll
            for (int h = 0; h < 2; h++) {
                const int ch = tid + h * 256;       // 512 chunks: 32 rows x 16
                const int row = ch >> 4;
                const int cc  = ch & 15;
                cp_async16(smem_u32(&Bs[s][row][cc * 8]),
                           Bb + (long)(k0 + row) * ldb + cc * 8);
            }
        } else {
#pragma unroll
            for (int half = 0; half < 2; half++) {
                const int row = r0 + half * 64;
                cp_async16(smem_u32(&Bs[s][row][c0 * 8]),
                           Bb + (long)row * ldb + k0 + c0 * 8);
            }
        }
    };

    wmma::fragment<wmma::accumulator, 16, 16, 16, float> acc[2][4];
#pragma unroll
    for (int i = 0; i < 2; i++)
#pragma unroll
        for (int j = 0; j < 4; j++) wmma::fill_fragment(acc[i][j], 0.0f);

    load_stage(0, kBeg);
    CP_COMMIT();

    for (int kt = 0; kt < ntiles; kt++) {
        if (kt + 1 < ntiles) {
            load_stage((kt + 1) & 1, kBeg + (kt + 1) * BK);
            CP_COMMIT();
            CP_WAIT(1);
        } else {
            CP_WAIT(0);
        }
        __syncthreads();

        const int s = kt & 1;
#pragma unroll
        for (int ks = 0; ks < BK; ks += 16) {
            wmma::fragment<wmma::matrix_a, 16, 16, 16, __nv_bfloat16, wmma::row_major> af[2];
#pragma unroll
            for (int i = 0; i < 2; i++)
                wmma::load_matrix_sync(af[i], &As[s][wm * 32 + i * 16][ks], LDSA);
            if (BNN) {
                wmma::fragment<wmma::matrix_b, 16, 16, 16, __nv_bfloat16, wmma::row_major> bf[4];
#pragma unroll
                for (int j = 0; j < 4; j++)
                    wmma::load_matrix_sync(bf[j], &Bs[s][ks][wn * 64 + j * 16], BCOLS);
#pragma unroll
                for (int i = 0; i < 2; i++)
#pragma unroll
                    for (int j = 0; j < 4; j++)
                        wmma::mma_sync(acc[i][j], af[i], bf[j], acc[i][j]);
            } else {
                wmma::fragment<wmma::matrix_b, 16, 16, 16, __nv_bfloat16, wmma::col_major> bf[4];
#pragma unroll
                for (int j = 0; j < 4; j++)
                    wmma::load_matrix_sync(bf[j], &Bs[s][wn * 64 + j * 16][ks], BCOLS);
#pragma unroll
                for (int i = 0; i < 2; i++)
#pragma unroll
                    for (int j = 0; j < 4; j++)
                        wmma::mma_sync(acc[i][j], af[i], bf[j], acc[i][j]);
            }
        }
        __syncthreads();
    }

    if (OUTBF == 0) {
        float* Cb = (float*)Cv + (long)b * strideC + (long)sp * partStride;
#pragma unroll
        for (int i = 0; i < 2; i++) {
            const int row0 = blockIdx.y * 128 + wm * 32 + i * 16;
#pragma unroll
            for (int j = 0; j < 4; j++) {
                const int col0 = blockIdx.x * 128 + wn * 64 + j * 16;
                wmma::store_matrix_sync(&Cb[(long)row0 * ldc + col0], acc[i][j],
                                        ldc, wmma::mem_row_major);
            }
        }
    } else {
        // bf16 store: stage per-warp 16x64 strip in SMEM, coalesced 128B rows.
        __nv_bfloat16* Cb = (__nv_bfloat16*)Cv + (long)b * strideC;
        float* stg = reinterpret_cast<float*>(&As[0][0][0]) + wid * (16 * 72);
        const int lane = tid & 31;
        const int col0 = blockIdx.x * 128 + wn * 64;
#pragma unroll
        for (int i = 0; i < 2; i++) {
            const int row0 = blockIdx.y * 128 + wm * 32 + i * 16;
#pragma unroll
            for (int j = 0; j < 4; j++)
                wmma::store_matrix_sync(stg + j * 16, acc[i][j], 72, wmma::mem_row_major);
            __syncwarp();
#pragma unroll
            for (int rr = 0; rr < 4; rr++) {
                const int r  = rr * 4 + (lane >> 3);
                const int cc = (lane & 7) * 8;
                __nv_bfloat16 tmp[8];
#pragma unroll
                for (int e = 0; e < 8; e++)
                    tmp[e] = __float2bfloat16(stg[r * 72 + cc + e]);
                *(uint4*)(Cb + (long)(row0 + r) * ldc + col0 + cc) = *(uint4*)tmp;
            }
            __syncwarp();
        }
    }
}

// ---------------------------------------------------------------------------
// fp32 [rows,cols] -> bf16 straight + bf16 transposed
// ---------------------------------------------------------------------------
__global__ __launch_bounds__(256) void convT_kernel(
    const float* __restrict__ X, __nv_bfloat16* __restrict__ Xbf,
    __nv_bfloat16* __restrict__ XT, int rows, int cols)
{
    __shared__ float t[32][33];
    const long bofs = (long)blockIdx.z * rows * cols;
    const int c0 = blockIdx.x * 32, r0 = blockIdx.y * 32;
    const int tx = threadIdx.x & 31, ty = threadIdx.x >> 5;
#pragma unroll
    for (int i = ty; i < 32; i += 8) {
        float v = X[bofs + (long)(r0 + i) * cols + c0 + tx];
        t[i][tx] = v;
        Xbf[bofs + (long)(r0 + i) * cols + c0 + tx] = __float2bfloat16(v);
    }
    __syncthreads();
#pragma unroll
    for (int i = ty; i < 32; i += 8)
        XT[bofs + (long)(c0 + i) * rows + r0 + tx] = __float2bfloat16(t[tx][i]);
}

__global__ __launch_bounds__(256) void convW_kernel(
    const float* __restrict__ W, __nv_bfloat16* __restrict__ Wb, int n)
{
    int i = blockIdx.x * 256 + threadIdx.x;
    if (i < n) Wb[i] = __float2bfloat16(W[i]);
}

__global__ void zeroS_kernel(float* S)
{
    int i = blockIdx.x * 256 + threadIdx.x;
    if (i < NB * 2 * NREG) S[i] = 0.f;
}

// ---------------------------------------------------------------------------
// Row softmax over 512 (+bias fold): bf16 logits -> P^T bf16. One warp/row.
// ---------------------------------------------------------------------------
__global__ __launch_bounds__(256) void softmax_rows_kernel(
    const __nv_bfloat16* __restrict__ L, const float* __restrict__ bias,
    __nv_bfloat16* __restrict__ PT)
{
    const long row = (long)blockIdx.x * 8 + (threadIdx.x >> 5);
    const int lane = threadIdx.x & 31;
    const __nv_bfloat16* rp = L + row * NREG;
    float v[16];
    float mx = -1e30f;
#pragma unroll
    for (int i = 0; i < 16; i++) {
        v[i] = __bfloat162float(rp[lane + i * 32]) + bias[lane + i * 32];
        mx = fmaxf(mx, v[i]);
    }
#pragma unroll
    for (int o = 16; o > 0; o >>= 1) mx = fmaxf(mx, __shfl_xor_sync(0xffffffffu, mx, o));
    float s = 0.f;
#pragma unroll
    for (int i = 0; i < 16; i++) { v[i] = __expf(v[i] - mx); s += v[i]; }
#pragma unroll
    for (int o = 16; o > 0; o >>= 1) s += __shfl_xor_sync(0xffffffffu, s, o);
    const float inv = 1.f / s;
    __nv_bfloat16* pp = PT + row * NREG;
#pragma unroll
    for (int i = 0; i < 16; i++) pp[lane + i * 32] = __float2bfloat16(v[i] * inv);
}

// ---------------------------------------------------------------------------
// Column sums of PT: S[b][which][j] += sum_n PT[b][n][j]. Coalesced.
// ---------------------------------------------------------------------------
__global__ __launch_bounds__(256) void rowsumT_kernel(
    const __nv_bfloat16* __restrict__ PT, float* __restrict__ S, int which)
{
    const int b = blockIdx.y;
    const int tid = threadIdx.x;
    const __nv_bfloat16* base =
        PT + (long)b * NPIX * NREG + (long)blockIdx.x * 64 * NREG;
    float v0 = 0.f, v1 = 0.f;
#pragma unroll 4
    for (int r = 0; r < 64; r++) {
        v0 += __bfloat162float(base[(long)r * NREG + tid]);
        v1 += __bfloat162float(base[(long)r * NREG + tid + 256]);
    }
    float* Sb = S + ((long)b * 2 + which) * NREG;
    atomicAdd(&Sb[tid], v0);
    atomicAdd(&Sb[tid + 256], v1);
}

// ---------------------------------------------------------------------------
// Reduce KSPLIT_G partials
// ---------------------------------------------------------------------------
__global__ __launch_bounds__(256) void reduceG_kernel(
    const float* __restrict__ Gp, float* __restrict__ G, int n, long part)
{
    int i = blockIdx.x * 256 + threadIdx.x;
    if (i < n)
        G[i] = Gp[i] + Gp[i + part] + Gp[i + 2 * part] + Gp[i + 3 * part];
}

// ---------------------------------------------------------------------------
// Final elementwise: out = tgt + alpha*(rawbf + bout[c]); 8 elems/thread.
// ---------------------------------------------------------------------------
__global__ __launch_bounds__(256) void final_ep_kernel(
    const __nv_bfloat16* __restrict__ rawbf, const float* __restrict__ tgt,
    const float* __restrict__ bout, const float* __restrict__ alphap,
    float* __restrict__ out)
{
    const long i8 = (long)blockIdx.x * 256 + threadIdx.x;
    const long base = i8 * 8;
    const int c = (int)((base / NPIX) % NC);
    const float alpha = *alphap;
    const float bv = bout[c];
    __nv_bfloat16 rv[8];
    *(uint4*)rv = *(const uint4*)(rawbf + base);
    float4 t0 = *(const float4*)(tgt + base);
    float4 t1 = *(const float4*)(tgt + base + 4);
    float4 o0, o1;
    o0.x = t0.x + alpha * (__bfloat162float(rv[0]) + bv);
    o0.y = t0.y + alpha * (__bfloat162float(rv[1]) + bv);
    o0.z = t0.z + alpha * (__bfloat162float(rv[2]) + bv);
    o0.w = t0.w + alpha * (__bfloat162float(rv[3]) + bv);
    o1.x = t1.x + alpha * (__bfloat162float(rv[4]) + bv);
    o1.y = t1.y + alpha * (__bfloat162float(rv[5]) + bv);
    o1.z = t1.z + alpha * (__bfloat162float(rv[6]) + bv);
    o1.w = t1.w + alpha * (__bfloat162float(rv[7]) + bv);
    *(float4*)(out + base)     = o0;
    *(float4*)(out + base + 4) = o1;
}

// ---------------------------------------------------------------------------
// Per-(b,h) region attention -> M (bf16)
// ---------------------------------------------------------------------------
__global__ __launch_bounds__(128) void region_attn_kernel(
    const float* __restrict__ G, const float* __restrict__ S,
    const float* __restrict__ Wq,  const float* __restrict__ bq,
    const float* __restrict__ Wkv, const float* __restrict__ bkv,
    const float* __restrict__ Wout,
    __nv_bfloat16* __restrict__ M)
{
    const int h = blockIdx.x, b = blockIdx.y;
    const float* Gt = G + ((long)b * 2 + 0) * NC * NREG;
    const float* Gs = G + ((long)b * 2 + 1) * NC * NREG;
    const float* Sq = S + ((long)b * 2 + 0) * NREG;
    const float* Sk = S + ((long)b * 2 + 1) * NREG;

    __shared__ float qr[32][64];
    __shared__ float kr[32][64];
    __shared__ float vr[32][64];
    __shared__ float attn[64][65];

    const int tid = threadIdx.x;

    for (int idx = tid; idx < 32 * 64; idx += 128) {
        const int d = idx >> 6, r = idx & 63;
        const int row = h * 32 + d, j = h * 64 + r;
        float s0 = 0.f, s1 = 0.f;
        for (int c = 0; c < 256; c += 2) {
            s0 += Wq[row * 256 + c + 0] * Gt[(c + 0) * NREG + j];
            s1 += Wq[row * 256 + c + 1] * Gt[(c + 1) * NREG + j];
        }
        qr[d][r] = s0 + s1 + bq[row] * Sq[j];
    }
    for (int idx = tid; idx < 32 * 64; idx += 128) {
        const int d = idx >> 6, r = idx & 63;
        const int rk = h * 64 + d, rv = h * 64 + 32 + d, j = h * 64 + r;
        float sk = 0.f, sv = 0.f;
        for (int c = 0; c < 256; c++) {
            const float g = Gs[c * NREG + j];
            sk += Wkv[rk * 256 + c] * g;
            sv += Wkv[rv * 256 + c] * g;
        }
        kr[d][r] = sk + bkv[rk] * Sk[j];
        vr[d][r] = sv + bkv[rv] * Sk[j];
    }
    __syncthreads();

    const float scale = rsqrtf((float)NHD);
    for (int idx = tid; idx < 64 * 64; idx += 128) {
        const int qi = idx >> 6, ki = idx & 63;
        float s = 0.f;
#pragma unroll
        for (int d = 0; d < 32; d++) s += qr[d][qi] * kr[d][ki];
        attn[qi][ki] = s * scale;
    }
    __syncthreads();

    if (tid < 64) {
        float mx = -1e30f;
        for (int k = 0; k < 64; k++) mx = fmaxf(mx, attn[tid][k]);
        float s = 0.f;
        for (int k = 0; k < 64; k++) {
            const float e = __expf(attn[tid][k] - mx);
            attn[tid][k] = e;
            s += e;
        }
        const float inv = 1.f / s;
        for (int k = 0; k < 64; k++) attn[tid][k] *= inv;
    }
    __syncthreads();

    for (int idx = tid; idx < 32 * 64; idx += 128) {
        const int d = idx >> 6, qi = idx & 63;
        float s = 0.f;
#pragma unroll
        for (int k = 0; k < 64; k++) s += vr[d][k] * attn[qi][k];
        qr[d][qi] = s;
    }
    __syncthreads();

    for (int idx = tid; idx < 256 * 64; idx += 128) {
        const int c = idx >> 6, r = idx & 63;
        float s = 0.f;
#pragma unroll
        for (int d = 0; d < 32; d++) s += Wout[c * 256 + h * 32 + d] * qr[d][r];
        M[((long)b * NC + c) * NREG + h * 64 + r] = __float2bfloat16(s);
    }
}

// ---------------------------------------------------------------------------
// Launch
// ---------------------------------------------------------------------------
extern "C" void kernel_launch(void* const* d_in, const int* in_sizes, int n_in,
                              void* d_out, int out_size)
{
    const float* src  = (const float*)d_in[0];
    const float* tgt  = (const float*)d_in[1];
    const float* Wq   = (const float*)d_in[2];
    const float* bq   = (const float*)d_in[3];
    const float* Wkv  = (const float*)d_in[4];
    const float* bkv  = (const float*)d_in[5];
    const float* Wrq  = (const float*)d_in[6];
    const float* brq  = (const float*)d_in[7];
    const float* Wrk  = (const float*)d_in[8];
    const float* brk  = (const float*)d_in[9];
    const float* Wout = (const float*)d_in[10];
    const float* bout = (const float*)d_in[11];
    const float* alpha = (const float*)d_in[12];
    float* out = (float*)d_out;

    float *Gp, *G, *S;
    __nv_bfloat16 *Lbf, *PqT, *PkT, *tgt_bf, *src_bf, *tgtT, *srcT, *Wrq_bf, *Wrk_bf, *Mbf;
    cudaGetSymbolAddress((void**)&Lbf,    g_Lbf);
    cudaGetSymbolAddress((void**)&PqT,    g_PqT);
    cudaGetSymbolAddress((void**)&PkT,    g_PkT);
    cudaGetSymbolAddress((void**)&tgt_bf, g_tgt_bf);
    cudaGetSymbolAddress((void**)&src_bf, g_src_bf);
    cudaGetSymbolAddress((void**)&tgtT,   g_tgtT_bf);
    cudaGetSymbolAddress((void**)&srcT,   g_srcT_bf);
    cudaGetSymbolAddress((void**)&Wrq_bf, g_Wrq_bf);
    cudaGetSymbolAddress((void**)&Wrk_bf, g_Wrk_bf);
    cudaGetSymbolAddress((void**)&Gp,     g_Gp);
    cudaGetSymbolAddress((void**)&G,      g_G);
    cudaGetSymbolAddress((void**)&S,      g_S);
    cudaGetSymbolAddress((void**)&Mbf,    g_Mbf);

    const long GTOT = (long)NB * 2 * NC * NREG;

    // 0) conversions + S zero
    convT_kernel<<<dim3(NPIX / 32, NC / 32, NB), 256>>>(tgt, tgt_bf, tgtT, NC, NPIX);
    convT_kernel<<<dim3(NPIX / 32, NC / 32, NB), 256>>>(src, src_bf, srcT, NC, NPIX);
    convW_kernel<<<(NREG * NC + 255) / 256, 256>>>(Wrq, Wrq_bf, NREG * NC);
    convW_kernel<<<(NREG * NC + 255) / 256, 256>>>(Wrk, Wrk_bf, NREG * NC);
    zeroS_kernel<<<(NB * 2 * NREG + 255) / 256, 256>>>(S);

    // 1q) bf16 logits Lq = tgtT . Wrq^T ; softmax(+brq) -> PqT ; column-sum
    gemm_wmma_kernel<0, 1><<<dim3(NREG / 128, NPIX / 128, NB), 256>>>(
        tgtT, NC, (long)NPIX * NC, Wrq_bf, NC, 0,
        Lbf, NREG, (long)NPIX * NREG, 0, NC, 1);
    softmax_rows_kernel<<<NB * NPIX / 8, 256>>>(Lbf, brq, PqT);
    rowsumT_kernel<<<dim3(NPIX / 64, NB), 256>>>(PqT, S, 0);

    // 1k) same for k
    gemm_wmma_kernel<0, 1><<<dim3(NREG / 128, NPIX / 128, NB), 256>>>(
        srcT, NC, (long)NPIX * NC, Wrk_bf, NC, 0,
        Lbf, NREG, (long)NPIX * NREG, 0, NC, 1);
    softmax_rows_kernel<<<NB * NPIX / 8, 256>>>(Lbf, brk, PkT);
    rowsumT_kernel<<<dim3(NPIX / 64, NB), 256>>>(PkT, S, 1);

    // 2) G matrices: NN GEMMs reading PT directly; K-split partials, reduce
    gemm_wmma_kernel<1, 0><<<dim3(NREG / 128, NC / 128, NB * KSPLIT_G), 256>>>(
        tgt_bf, NPIX, (long)NC * NPIX, PqT, NREG, (long)NPIX * NREG,
        Gp, NREG, (long)2 * NC * NREG, GTOT, NPIX, KSPLIT_G);
    gemm_wmma_kernel<1, 0><<<dim3(NREG / 128, NC / 128, NB * KSPLIT_G), 256>>>(
        src_bf, NPIX, (long)NC * NPIX, PkT, NREG, (long)NPIX * NREG,
        Gp + (long)NC * NREG, NREG, (long)2 * NC * NREG, GTOT, NPIX, KSPLIT_G);
    reduceG_kernel<<<(int)((GTOT + 255) / 256), 256>>>(Gp, G, (int)GTOT, GTOT);

    // 3) small attention -> M (bf16)
    region_attn_kernel<<<dim3(NHEAD, NB), 128>>>(G, S, Wq, bq, Wkv, bkv, Wout, Mbf);

    // 4) bf16 raw final = M . Pq (B = PqT, NT form), then coalesced residual pass
    gemm_wmma_kernel<0, 1><<<dim3(NPIX / 128, NC / 128, NB), 256>>>(
        Mbf, NREG, (long)NC * NREG, PqT, NREG, (long)NPIX * NREG,
        Lbf, NPIX, (long)NC * NPIX, 0, NREG, 1);
    final_ep_kernel<<<(int)((long)NB * NC * NPIX / 8 / 256), 256>>>(
        Lbf, tgt, bout, alpha, out);

    (void)in_sizes; (void)n_in; (void)out_size;
}

// round 17
// speedup vs baseline: 1.2434x; 1.0781x over previous
#include <cuda_runtime.h>
#include <cuda_bf16.h>
#include <mma.h>
#include <cstdint>

using namespace nvcuda;

// ---------------------------------------------------------------------------
// Problem constants
// ---------------------------------------------------------------------------
#define NB    8
#define NPIX  9216     // 96*96
#define NREG  512      // R*HEADS
#define NC    256      // channels / E
#define NHEAD 8
#define NHD   32
#define KSPLIT_G 4

// GEMM tile config (BK=64, dynamic SMEM)
#define GEMM_BK    64
#define LDSA_E     80           // A row stride in bf16 elems (160 B, 32B-mult)
#define BCOLS_NN   144          // NN B row stride in elems (288 B, 32B-mult)
#define ASTAGE_E   (128 * LDSA_E)          // elems per A stage
#define BSTAGE_NT_E (128 * LDSA_E)
#define BSTAGE_NN_E (64 * BCOLS_NN)
#define SMEM_NT_BYTES (2 * (ASTAGE_E + BSTAGE_NT_E) * 2 + 32)   // 81952
#define SMEM_NN_BYTES ((2 * ASTAGE_E + 2 * BSTAGE_NN_E) * 2 + 32) // 77856

// ---------------------------------------------------------------------------
// Scratch (device globals)
// ---------------------------------------------------------------------------
__device__ __nv_bfloat16 g_Lbf [(size_t)NB * NPIX * NREG];   // bf16 logits / bf16 final raw
__device__ __nv_bfloat16 g_PqT [(size_t)NB * NPIX * NREG];
__device__ __nv_bfloat16 g_PkT [(size_t)NB * NPIX * NREG];
__device__ __nv_bfloat16 g_tgt_bf [(size_t)NB * NC * NPIX];
__device__ __nv_bfloat16 g_src_bf [(size_t)NB * NC * NPIX];
__device__ __nv_bfloat16 g_tgtT_bf[(size_t)NB * NPIX * NC];
__device__ __nv_bfloat16 g_srcT_bf[(size_t)NB * NPIX * NC];
__device__ __nv_bfloat16 g_Wrq_bf[NREG * NC];
__device__ __nv_bfloat16 g_Wrk_bf[NREG * NC];
__device__ float         g_Gp  [(size_t)KSPLIT_G * NB * 2 * NC * NREG];
__device__ float         g_G   [(size_t)NB * 2 * NC * NREG];
__device__ float         g_S   [(size_t)NB * 2 * NREG];
__device__ __nv_bfloat16 g_Mbf [(size_t)NB * NC * NREG];

// ---------------------------------------------------------------------------
// cp.async helpers
// ---------------------------------------------------------------------------
__device__ __forceinline__ uint32_t smem_u32(const void* p) {
    uint32_t a;
    asm("{ .reg .u64 t; cvta.to.shared.u64 t, %1; cvt.u32.u64 %0, t; }"
        : "=r"(a) : "l"(p));
    return a;
}
__device__ __forceinline__ void cp_async16(uint32_t dst, const void* src) {
    asm volatile("cp.async.cg.shared.global [%0], [%1], 16;\n" :: "r"(dst), "l"(src));
}
#define CP_COMMIT()  asm volatile("cp.async.commit_group;\n" ::: "memory")
#define CP_WAIT(n)   asm volatile("cp.async.wait_group %0;\n" :: "n"(n) : "memory")

// ---------------------------------------------------------------------------
// WMMA bf16 GEMM, CTA tile 128x128, BK=64, 8 warps (4x2), warp tile 32x64.
// Dynamic SMEM (2-stage double buffer).
// BNN=0: B is K-major [n][k]   (NT form, col_major b-frags).
// BNN=1: B is N-major [k][n]   (NN form, row_major b-frags) -- reads PT directly.
// OUTBF=0: raw fp32 store (+optional ksplit partial offset partStride).
// OUTBF=1: bf16 store via SMEM staging, coalesced 128B row writes.
// ---------------------------------------------------------------------------
template<int BNN, int OUTBF>
__global__ __launch_bounds__(256) void gemm_wmma_kernel(
    const __nv_bfloat16* __restrict__ A, int lda, long strideA,
    const __nv_bfloat16* __restrict__ B, int ldb, long strideB,
    void* __restrict__ Cv, int ldc, long strideC, long partStride,
    int K, int ksplit)
{
    constexpr int BK = GEMM_BK;
    constexpr int BSTAGE_E = BNN ? BSTAGE_NN_E : BSTAGE_NT_E;

    extern __shared__ char dyn_raw[];
    // round base up to 32 B for WMMA alignment
    uintptr_t base_i = ((uintptr_t)dyn_raw + 31) & ~(uintptr_t)31;
    __nv_bfloat16* AsP = (__nv_bfloat16*)base_i;                 // 2 stages
    __nv_bfloat16* BsP = AsP + 2 * ASTAGE_E;                     // 2 stages

    const int tid  = threadIdx.x;
    const int wid  = tid >> 5;
    const int wm   = wid & 3;
    const int wn   = wid >> 2;

    const int b  = blockIdx.z / ksplit;
    const int sp = blockIdx.z % ksplit;
    const int klen = K / ksplit;
    const int kBeg = sp * klen;
    const int ntiles = klen / BK;

    const __nv_bfloat16* Ab = A + (long)b * strideA + (long)(blockIdx.y * 128) * lda;
    const __nv_bfloat16* Bb;
    if (BNN) Bb = B + (long)b * strideB + blockIdx.x * 128;               // col offset
    else     Bb = B + (long)b * strideB + (long)(blockIdx.x * 128) * ldb; // row offset

    const uint32_t AsU = smem_u32(AsP);
    const uint32_t BsU = smem_u32(BsP);

    auto load_stage = [&](int s, int k0) {
        // A: 128 rows x 64 bf16 = 1024 16B chunks, 4 per thread
#pragma unroll
        for (int h = 0; h < 4; h++) {
            const int ch  = tid + h * 256;
            const int row = ch >> 3;          // 0..127
            const int cc  = ch & 7;           // 0..7
            cp_async16(AsU + (s * ASTAGE_E + row * LDSA_E + cc * 8) * 2,
                       Ab + (long)row * lda + k0 + cc * 8);
        }
        if (BNN) {
            // B: 64 rows x 128 cols = 1024 chunks
#pragma unroll
            for (int h = 0; h < 4; h++) {
                const int ch  = tid + h * 256;
                const int row = ch >> 4;      // 0..63
                const int cc  = ch & 15;      // 0..15
                cp_async16(BsU + (s * BSTAGE_E + row * BCOLS_NN + cc * 8) * 2,
                           Bb + (long)(k0 + row) * ldb + cc * 8);
            }
        } else {
#pragma unroll
            for (int h = 0; h < 4; h++) {
                const int ch  = tid + h * 256;
                const int row = ch >> 3;
                const int cc  = ch & 7;
                cp_async16(BsU + (s * BSTAGE_E + row * LDSA_E + cc * 8) * 2,
                           Bb + (long)row * ldb + k0 + cc * 8);
            }
        }
    };

    wmma::fragment<wmma::accumulator, 16, 16, 16, float> acc[2][4];
#pragma unroll
    for (int i = 0; i < 2; i++)
#pragma unroll
        for (int j = 0; j < 4; j++) wmma::fill_fragment(acc[i][j], 0.0f);

    load_stage(0, kBeg);
    CP_COMMIT();

    for (int kt = 0; kt < ntiles; kt++) {
        if (kt + 1 < ntiles) {
            load_stage((kt + 1) & 1, kBeg + (kt + 1) * BK);
            CP_COMMIT();
            CP_WAIT(1);
        } else {
            CP_WAIT(0);
        }
        __syncthreads();

        const int s = kt & 1;
#pragma unroll
        for (int ks = 0; ks < BK; ks += 16) {
            wmma::fragment<wmma::matrix_a, 16, 16, 16, __nv_bfloat16, wmma::row_major> af[2];
#pragma unroll
            for (int i = 0; i < 2; i++)
                wmma::load_matrix_sync(af[i],
                    AsP + s * ASTAGE_E + (wm * 32 + i * 16) * LDSA_E + ks, LDSA_E);
            if (BNN) {
                wmma::fragment<wmma::matrix_b, 16, 16, 16, __nv_bfloat16, wmma::row_major> bf[4];
#pragma unroll
                for (int j = 0; j < 4; j++)
                    wmma::load_matrix_sync(bf[j],
                        BsP + s * BSTAGE_E + ks * BCOLS_NN + wn * 64 + j * 16, BCOLS_NN);
#pragma unroll
                for (int i = 0; i < 2; i++)
#pragma unroll
                    for (int j = 0; j < 4; j++)
                        wmma::mma_sync(acc[i][j], af[i], bf[j], acc[i][j]);
            } else {
                wmma::fragment<wmma::matrix_b, 16, 16, 16, __nv_bfloat16, wmma::col_major> bf[4];
#pragma unroll
                for (int j = 0; j < 4; j++)
                    wmma::load_matrix_sync(bf[j],
                        BsP + s * BSTAGE_E + (wn * 64 + j * 16) * LDSA_E + ks, LDSA_E);
#pragma unroll
                for (int i = 0; i < 2; i++)
#pragma unroll
                    for (int j = 0; j < 4; j++)
                        wmma::mma_sync(acc[i][j], af[i], bf[j], acc[i][j]);
            }
        }
        __syncthreads();
    }

    if (OUTBF == 0) {
        float* Cb = (float*)Cv + (long)b * strideC + (long)sp * partStride;
#pragma unroll
        for (int i = 0; i < 2; i++) {
            const int row0 = blockIdx.y * 128 + wm * 32 + i * 16;
#pragma unroll
            for (int j = 0; j < 4; j++) {
                const int col0 = blockIdx.x * 128 + wn * 64 + j * 16;
                wmma::store_matrix_sync(&Cb[(long)row0 * ldc + col0], acc[i][j],
                                        ldc, wmma::mem_row_major);
            }
        }
    } else {
        // bf16 store: stage per-warp 16x64 strip in SMEM, coalesced 128B rows.
        __nv_bfloat16* Cb = (__nv_bfloat16*)Cv + (long)b * strideC;
        float* stg = reinterpret_cast<float*>(AsP) + wid * (16 * 72);
        const int lane = tid & 31;
        const int col0 = blockIdx.x * 128 + wn * 64;
#pragma unroll
        for (int i = 0; i < 2; i++) {
            const int row0 = blockIdx.y * 128 + wm * 32 + i * 16;
#pragma unroll
            for (int j = 0; j < 4; j++)
                wmma::store_matrix_sync(stg + j * 16, acc[i][j], 72, wmma::mem_row_major);
            __syncwarp();
#pragma unroll
            for (int rr = 0; rr < 4; rr++) {
                const int r  = rr * 4 + (lane >> 3);
                const int cc = (lane & 7) * 8;
                __nv_bfloat16 tmp[8];
#pragma unroll
                for (int e = 0; e < 8; e++)
                    tmp[e] = __float2bfloat16(stg[r * 72 + cc + e]);
                *(uint4*)(Cb + (long)(row0 + r) * ldc + col0 + cc) = *(uint4*)tmp;
            }
            __syncwarp();
        }
    }
}

// ---------------------------------------------------------------------------
// fp32 [rows,cols] -> bf16 straight + bf16 transposed
// ---------------------------------------------------------------------------
__global__ __launch_bounds__(256) void convT_kernel(
    const float* __restrict__ X, __nv_bfloat16* __restrict__ Xbf,
    __nv_bfloat16* __restrict__ XT, int rows, int cols)
{
    __shared__ float t[32][33];
    const long bofs = (long)blockIdx.z * rows * cols;
    const int c0 = blockIdx.x * 32, r0 = blockIdx.y * 32;
    const int tx = threadIdx.x & 31, ty = threadIdx.x >> 5;
#pragma unroll
    for (int i = ty; i < 32; i += 8) {
        float v = X[bofs + (long)(r0 + i) * cols + c0 + tx];
        t[i][tx] = v;
        Xbf[bofs + (long)(r0 + i) * cols + c0 + tx] = __float2bfloat16(v);
    }
    __syncthreads();
#pragma unroll
    for (int i = ty; i < 32; i += 8)
        XT[bofs + (long)(c0 + i) * rows + r0 + tx] = __float2bfloat16(t[tx][i]);
}

__global__ __launch_bounds__(256) void convW_kernel(
    const float* __restrict__ W, __nv_bfloat16* __restrict__ Wb, int n)
{
    int i = blockIdx.x * 256 + threadIdx.x;
    if (i < n) Wb[i] = __float2bfloat16(W[i]);
}

__global__ void zeroS_kernel(float* S)
{
    int i = blockIdx.x * 256 + threadIdx.x;
    if (i < NB * 2 * NREG) S[i] = 0.f;
}

// ---------------------------------------------------------------------------
// Row softmax over 512 (+bias fold): bf16 logits -> P^T bf16. One warp/row.
// ---------------------------------------------------------------------------
__global__ __launch_bounds__(256) void softmax_rows_kernel(
    const __nv_bfloat16* __restrict__ L, const float* __restrict__ bias,
    __nv_bfloat16* __restrict__ PT)
{
    const long row = (long)blockIdx.x * 8 + (threadIdx.x >> 5);
    const int lane = threadIdx.x & 31;
    const __nv_bfloat16* rp = L + row * NREG;
    float v[16];
    float mx = -1e30f;
#pragma unroll
    for (int i = 0; i < 16; i++) {
        v[i] = __bfloat162float(rp[lane + i * 32]) + bias[lane + i * 32];
        mx = fmaxf(mx, v[i]);
    }
#pragma unroll
    for (int o = 16; o > 0; o >>= 1) mx = fmaxf(mx, __shfl_xor_sync(0xffffffffu, mx, o));
    float s = 0.f;
#pragma unroll
    for (int i = 0; i < 16; i++) { v[i] = __expf(v[i] - mx); s += v[i]; }
#pragma unroll
    for (int o = 16; o > 0; o >>= 1) s += __shfl_xor_sync(0xffffffffu, s, o);
    const float inv = 1.f / s;
    __nv_bfloat16* pp = PT + row * NREG;
#pragma unroll
    for (int i = 0; i < 16; i++) pp[lane + i * 32] = __float2bfloat16(v[i] * inv);
}

// ---------------------------------------------------------------------------
// Column sums of PT: S[b][which][j] += sum_n PT[b][n][j]. Coalesced.
// ---------------------------------------------------------------------------
__global__ __launch_bounds__(256) void rowsumT_kernel(
    const __nv_bfloat16* __restrict__ PT, float* __restrict__ S, int which)
{
    const int b = blockIdx.y;
    const int tid = threadIdx.x;
    const __nv_bfloat16* base =
        PT + (long)b * NPIX * NREG + (long)blockIdx.x * 64 * NREG;
    float v0 = 0.f, v1 = 0.f;
#pragma unroll 4
    for (int r = 0; r < 64; r++) {
        v0 += __bfloat162float(base[(long)r * NREG + tid]);
        v1 += __bfloat162float(base[(long)r * NREG + tid + 256]);
    }
    float* Sb = S + ((long)b * 2 + which) * NREG;
    atomicAdd(&Sb[tid], v0);
    atomicAdd(&Sb[tid + 256], v1);
}

// ---------------------------------------------------------------------------
// Reduce KSPLIT_G partials
// ---------------------------------------------------------------------------
__global__ __launch_bounds__(256) void reduceG_kernel(
    const float* __restrict__ Gp, float* __restrict__ G, int n, long part)
{
    int i = blockIdx.x * 256 + threadIdx.x;
    if (i < n)
        G[i] = Gp[i] + Gp[i + part] + Gp[i + 2 * part] + Gp[i + 3 * part];
}

// ---------------------------------------------------------------------------
// Final elementwise: out = tgt + alpha*(rawbf + bout[c]); 8 elems/thread.
// ---------------------------------------------------------------------------
__global__ __launch_bounds__(256) void final_ep_kernel(
    const __nv_bfloat16* __restrict__ rawbf, const float* __restrict__ tgt,
    const float* __restrict__ bout, const float* __restrict__ alphap,
    float* __restrict__ out)
{
    const long i8 = (long)blockIdx.x * 256 + threadIdx.x;
    const long base = i8 * 8;
    const int c = (int)((base / NPIX) % NC);
    const float alpha = *alphap;
    const float bv = bout[c];
    __nv_bfloat16 rv[8];
    *(uint4*)rv = *(const uint4*)(rawbf + base);
    float4 t0 = *(const float4*)(tgt + base);
    float4 t1 = *(const float4*)(tgt + base + 4);
    float4 o0, o1;
    o0.x = t0.x + alpha * (__bfloat162float(rv[0]) + bv);
    o0.y = t0.y + alpha * (__bfloat162float(rv[1]) + bv);
    o0.z = t0.z + alpha * (__bfloat162float(rv[2]) + bv);
    o0.w = t0.w + alpha * (__bfloat162float(rv[3]) + bv);
    o1.x = t1.x + alpha * (__bfloat162float(rv[4]) + bv);
    o1.y = t1.y + alpha * (__bfloat162float(rv[5]) + bv);
    o1.z = t1.z + alpha * (__bfloat162float(rv[6]) + bv);
    o1.w = t1.w + alpha * (__bfloat162float(rv[7]) + bv);
    *(float4*)(out + base)     = o0;
    *(float4*)(out + base + 4) = o1;
}

// ---------------------------------------------------------------------------
// Per-(b,h) region attention -> M (bf16)
// ---------------------------------------------------------------------------
__global__ __launch_bounds__(128) void region_attn_kernel(
    const float* __restrict__ G, const float* __restrict__ S,
    const float* __restrict__ Wq,  const float* __restrict__ bq,
    const float* __restrict__ Wkv, const float* __restrict__ bkv,
    const float* __restrict__ Wout,
    __nv_bfloat16* __restrict__ M)
{
    const int h = blockIdx.x, b = blockIdx.y;
    const float* Gt = G + ((long)b * 2 + 0) * NC * NREG;
    const float* Gs = G + ((long)b * 2 + 1) * NC * NREG;
    const float* Sq = S + ((long)b * 2 + 0) * NREG;
    const float* Sk = S + ((long)b * 2 + 1) * NREG;

    __shared__ float qr[32][64];
    __shared__ float kr[32][64];
    __shared__ float vr[32][64];
    __shared__ float attn[64][65];

    const int tid = threadIdx.x;

    for (int idx = tid; idx < 32 * 64; idx += 128) {
        const int d = idx >> 6, r = idx & 63;
        const int row = h * 32 + d, j = h * 64 + r;
        float s0 = 0.f, s1 = 0.f;
        for (int c = 0; c < 256; c += 2) {
            s0 += Wq[row * 256 + c + 0] * Gt[(c + 0) * NREG + j];
            s1 += Wq[row * 256 + c + 1] * Gt[(c + 1) * NREG + j];
        }
        qr[d][r] = s0 + s1 + bq[row] * Sq[j];
    }
    for (int idx = tid; idx < 32 * 64; idx += 128) {
        const int d = idx >> 6, r = idx & 63;
        const int rk = h * 64 + d, rv = h * 64 + 32 + d, j = h * 64 + r;
        float sk = 0.f, sv = 0.f;
        for (int c = 0; c < 256; c++) {
            const float g = Gs[c * NREG + j];
            sk += Wkv[rk * 256 + c] * g;
            sv += Wkv[rv * 256 + c] * g;
        }
        kr[d][r] = sk + bkv[rk] * Sk[j];
        vr[d][r] = sv + bkv[rv] * Sk[j];
    }
    __syncthreads();

    const float scale = rsqrtf((float)NHD);
    for (int idx = tid; idx < 64 * 64; idx += 128) {
        const int qi = idx >> 6, ki = idx & 63;
        float s = 0.f;
#pragma unroll
        for (int d = 0; d < 32; d++) s += qr[d][qi] * kr[d][ki];
        attn[qi][ki] = s * scale;
    }
    __syncthreads();

    if (tid < 64) {
        float mx = -1e30f;
        for (int k = 0; k < 64; k++) mx = fmaxf(mx, attn[tid][k]);
        float s = 0.f;
        for (int k = 0; k < 64; k++) {
            const float e = __expf(attn[tid][k] - mx);
            attn[tid][k] = e;
            s += e;
        }
        const float inv = 1.f / s;
        for (int k = 0; k < 64; k++) attn[tid][k] *= inv;
    }
    __syncthreads();

    for (int idx = tid; idx < 32 * 64; idx += 128) {
        const int d = idx >> 6, qi = idx & 63;
        float s = 0.f;
#pragma unroll
        for (int k = 0; k < 64; k++) s += vr[d][k] * attn[qi][k];
        qr[d][qi] = s;
    }
    __syncthreads();

    for (int idx = tid; idx < 256 * 64; idx += 128) {
        const int c = idx >> 6, r = idx & 63;
        float s = 0.f;
#pragma unroll
        for (int d = 0; d < 32; d++) s += Wout[c * 256 + h * 32 + d] * qr[d][r];
        M[((long)b * NC + c) * NREG + h * 64 + r] = __float2bfloat16(s);
    }
}

// ---------------------------------------------------------------------------
// Launch
// ---------------------------------------------------------------------------
extern "C" void kernel_launch(void* const* d_in, const int* in_sizes, int n_in,
                              void* d_out, int out_size)
{
    const float* src  = (const float*)d_in[0];
    const float* tgt  = (const float*)d_in[1];
    const float* Wq   = (const float*)d_in[2];
    const float* bq   = (const float*)d_in[3];
    const float* Wkv  = (const float*)d_in[4];
    const float* bkv  = (const float*)d_in[5];
    const float* Wrq  = (const float*)d_in[6];
    const float* brq  = (const float*)d_in[7];
    const float* Wrk  = (const float*)d_in[8];
    const float* brk  = (const float*)d_in[9];
    const float* Wout = (const float*)d_in[10];
    const float* bout = (const float*)d_in[11];
    const float* alpha = (const float*)d_in[12];
    float* out = (float*)d_out;

    float *Gp, *G, *S;
    __nv_bfloat16 *Lbf, *PqT, *PkT, *tgt_bf, *src_bf, *tgtT, *srcT, *Wrq_bf, *Wrk_bf, *Mbf;
    cudaGetSymbolAddress((void**)&Lbf,    g_Lbf);
    cudaGetSymbolAddress((void**)&PqT,    g_PqT);
    cudaGetSymbolAddress((void**)&PkT,    g_PkT);
    cudaGetSymbolAddress((void**)&tgt_bf, g_tgt_bf);
    cudaGetSymbolAddress((void**)&src_bf, g_src_bf);
    cudaGetSymbolAddress((void**)&tgtT,   g_tgtT_bf);
    cudaGetSymbolAddress((void**)&srcT,   g_srcT_bf);
    cudaGetSymbolAddress((void**)&Wrq_bf, g_Wrq_bf);
    cudaGetSymbolAddress((void**)&Wrk_bf, g_Wrk_bf);
    cudaGetSymbolAddress((void**)&Gp,     g_Gp);
    cudaGetSymbolAddress((void**)&G,      g_G);
    cudaGetSymbolAddress((void**)&S,      g_S);
    cudaGetSymbolAddress((void**)&Mbf,    g_Mbf);

    // Opt-in to >48KB dynamic SMEM. Called unconditionally every invocation
    // (idempotent, immediate, non-stream API; adds no graph nodes).
    cudaFuncSetAttribute(gemm_wmma_kernel<0, 1>,
                         cudaFuncAttributeMaxDynamicSharedMemorySize, SMEM_NT_BYTES);
    cudaFuncSetAttribute(gemm_wmma_kernel<1, 0>,
                         cudaFuncAttributeMaxDynamicSharedMemorySize, SMEM_NN_BYTES);

    const long GTOT = (long)NB * 2 * NC * NREG;

    // 0) conversions + S zero
    convT_kernel<<<dim3(NPIX / 32, NC / 32, NB), 256>>>(tgt, tgt_bf, tgtT, NC, NPIX);
    convT_kernel<<<dim3(NPIX / 32, NC / 32, NB), 256>>>(src, src_bf, srcT, NC, NPIX);
    convW_kernel<<<(NREG * NC + 255) / 256, 256>>>(Wrq, Wrq_bf, NREG * NC);
    convW_kernel<<<(NREG * NC + 255) / 256, 256>>>(Wrk, Wrk_bf, NREG * NC);
    zeroS_kernel<<<(NB * 2 * NREG + 255) / 256, 256>>>(S);

    // 1q) bf16 logits Lq = tgtT . Wrq^T ; softmax(+brq) -> PqT ; column-sum
    gemm_wmma_kernel<0, 1><<<dim3(NREG / 128, NPIX / 128, NB), 256, SMEM_NT_BYTES>>>(
        tgtT, NC, (long)NPIX * NC, Wrq_bf, NC, 0,
        Lbf, NREG, (long)NPIX * NREG, 0, NC, 1);
    softmax_rows_kernel<<<NB * NPIX / 8, 256>>>(Lbf, brq, PqT);
    rowsumT_kernel<<<dim3(NPIX / 64, NB), 256>>>(PqT, S, 0);

    // 1k) same for k
    gemm_wmma_kernel<0, 1><<<dim3(NREG / 128, NPIX / 128, NB), 256, SMEM_NT_BYTES>>>(
        srcT, NC, (long)NPIX * NC, Wrk_bf, NC, 0,
        Lbf, NREG, (long)NPIX * NREG, 0, NC, 1);
    softmax_rows_kernel<<<NB * NPIX / 8, 256>>>(Lbf, brk, PkT);
    rowsumT_kernel<<<dim3(NPIX / 64, NB), 256>>>(PkT, S, 1);

    // 2) G matrices: NN GEMMs reading PT directly; K-split partials, reduce
    gemm_wmma_kernel<1, 0><<<dim3(NREG / 128, NC / 128, NB * KSPLIT_G), 256, SMEM_NN_BYTES>>>(
        tgt_bf, NPIX, (long)NC * NPIX, PqT, NREG, (long)NPIX * NREG,
        Gp, NREG, (long)2 * NC * NREG, GTOT, NPIX, KSPLIT_G);
    gemm_wmma_kernel<1, 0><<<dim3(NREG / 128, NC / 128, NB * KSPLIT_G), 256, SMEM_NN_BYTES>>>(
        src_bf, NPIX, (long)NC * NPIX, PkT, NREG, (long)NPIX * NREG,
        Gp + (long)NC * NREG, NREG, (long)2 * NC * NREG, GTOT, NPIX, KSPLIT_G);
    reduceG_kernel<<<(int)((GTOT + 255) / 256), 256>>>(Gp, G, (int)GTOT, GTOT);

    // 3) small attention -> M (bf16)
    region_attn_kernel<<<dim3(NHEAD, NB), 128>>>(G, S, Wq, bq, Wkv, bkv, Wout, Mbf);

    // 4) bf16 raw final = M . Pq (B = PqT, NT form), then coalesced residual pass
    gemm_wmma_kernel<0, 1><<<dim3(NPIX / 128, NC / 128, NB), 256, SMEM_NT_BYTES>>>(
        Mbf, NREG, (long)NC * NREG, PqT, NREG, (long)NPIX * NREG,
        Lbf, NPIX, (long)NC * NPIX, 0, NREG, 1);
    final_ep_kernel<<<(int)((long)NB * NC * NPIX / 8 / 256), 256>>>(
        Lbf, tgt, bout, alpha, out);

    (void)in_sizes; (void)n_in; (void)out_size;
}